// round 3
// baseline (speedup 1.0000x reference)
#include <cuda_runtime.h>
#include <cstdint>

// BiCutLoss streaming reduction. 134MB output(f32) + 67MB labels(i32) read, 4B out.
// HBM-bound; goal = maximize achieved DRAM BW.
//  - __ldcs evict-first loads (no reuse, stop thrashing L2)
//  - exact-divisor grid (524288 threads, 8 iters/thread) + manual 4-wide batch
//    => 12 LDG.128 in flight per thread before consumption.

#define ALPHA 0.65f
#define RPAR  0.5f
#define C_POS ((1.0f - ALPHA) / RPAR)     // 0.7
#define C_NEG (ALPHA / (1.0f - RPAR))     // 1.3

static constexpr int THREADS = 256;
static constexpr int BLOCKS  = 2048;      // 2048*256 = 524288 threads; n4/threads = 8 exactly

__device__ __forceinline__ float group_val(const float4& o0, const float4& o1, const int4& l)
{
    float a = (l.x == 1) ? o0.x * C_POS : o0.y * C_NEG;
    float b = (l.y == 1) ? o0.z * C_POS : o0.w * C_NEG;
    float c = (l.z == 1) ? o1.x * C_POS : o1.y * C_NEG;
    float d = (l.w == 1) ? o1.z * C_POS : o1.w * C_NEG;
    return (a + b) + (c + d);
}

__global__ __launch_bounds__(THREADS)
void bicut_reduce_kernel(const float4* __restrict__ out4,  // 2 pairs per float4
                         const int4*   __restrict__ lab4,  // 4 labels per int4
                         float* __restrict__ res,
                         int n4,
                         float inv_b)
{
    const int tid    = blockIdx.x * blockDim.x + threadIdx.x;
    const int stride = gridDim.x * blockDim.x;

    float acc = 0.0f;

    int i = tid;
    // Main path: batches of 4 groups (12x LDG.128 front-batched, evict-first).
    for (; i + 3 * stride < n4; i += 4 * stride) {
        const int i0 = i;
        const int i1 = i + stride;
        const int i2 = i + 2 * stride;
        const int i3 = i + 3 * stride;

        float4 a0 = __ldcs(&out4[2 * i0 + 0]);
        float4 a1 = __ldcs(&out4[2 * i0 + 1]);
        float4 b0 = __ldcs(&out4[2 * i1 + 0]);
        float4 b1 = __ldcs(&out4[2 * i1 + 1]);
        float4 c0 = __ldcs(&out4[2 * i2 + 0]);
        float4 c1 = __ldcs(&out4[2 * i2 + 1]);
        float4 d0 = __ldcs(&out4[2 * i3 + 0]);
        float4 d1 = __ldcs(&out4[2 * i3 + 1]);
        int4   la = __ldcs(&lab4[i0]);
        int4   lb = __ldcs(&lab4[i1]);
        int4   lc = __ldcs(&lab4[i2]);
        int4   ld = __ldcs(&lab4[i3]);

        acc += group_val(a0, a1, la);
        acc += group_val(b0, b1, lb);
        acc += group_val(c0, c1, lc);
        acc += group_val(d0, d1, ld);
    }
    // Tail (0 iterations for the dataset shape, kept for generality).
    for (; i < n4; i += stride) {
        float4 o0 = __ldcs(&out4[2 * i + 0]);
        float4 o1 = __ldcs(&out4[2 * i + 1]);
        int4   l  = __ldcs(&lab4[i]);
        acc += group_val(o0, o1, l);
    }

    // Warp reduce
    #pragma unroll
    for (int off = 16; off > 0; off >>= 1)
        acc += __shfl_xor_sync(0xFFFFFFFFu, acc, off);

    // Block reduce via smem
    __shared__ float warp_sums[THREADS / 32];
    const int lane = threadIdx.x & 31;
    const int wid  = threadIdx.x >> 5;
    if (lane == 0) warp_sums[wid] = acc;
    __syncthreads();

    if (wid == 0) {
        acc = (lane < THREADS / 32) ? warp_sums[lane] : 0.0f;
        #pragma unroll
        for (int off = 4; off > 0; off >>= 1)
            acc += __shfl_xor_sync(0xFFFFFFFFu, acc, off);
        if (lane == 0)
            atomicAdd(res, acc * inv_b);
    }
}

extern "C" void kernel_launch(void* const* d_in, const int* in_sizes, int n_in,
                              void* d_out, int out_size)
{
    const float* output = (const float*)d_in[0];  // [B, L, 2] f32
    const int*   labels = (const int*)d_in[1];    // [B, L] int32

    const long long n_pairs = (long long)in_sizes[0] / 2;   // 16,777,216
    const int n4 = (int)(n_pairs / 4);                      // 4,194,304

    const float inv_b = 1.0f / 8192.0f;                     // B fixed by dataset

    float* res = (float*)d_out;
    cudaMemsetAsync(res, 0, sizeof(float));

    bicut_reduce_kernel<<<BLOCKS, THREADS>>>(
        (const float4*)output, (const int4*)labels, res, n4, inv_b);
}